// round 13
// baseline (speedup 1.0000x reference)
#include <cuda_runtime.h>
#include <cuda_fp16.h>
#include <cuda_bf16.h>
#include <cstdint>

#define NN 100000
#define EE 1600000
#define DD 128
#define AGG_BLOCKS 12500   // NN / 8 exactly

// ---------------- scratch (device globals; no runtime allocation) ----------------
__device__ uint2 g_h16[(size_t)NN * 32];        // fp16: GEMM out -> agg gather table
__device__ uint2 g_b16[(size_t)NN * 32];        // fp16: conv-agg out -> next GEMM in
__device__ uint2 g_r16[(size_t)NN * 32];        // fp16: layer0 out (residual)
__device__ uint2 g_l16[(size_t)NN * 32];        // fp16: LN out -> final GEMM in
__device__ unsigned short g_wth[4 * DD * DD];   // W^T hi (bf16 bits): W0,W1,W2,Wvo
__device__ unsigned short g_wtl[4 * DD * DD];   // W^T lo
__device__ float g_bvo[DD];
__device__ int   g_counts[NN];
__device__ int   g_off[NN + 1];
__device__ int   g_cursor[NN];
__device__ int   g_bsums[128];
__device__ float g_dinv[NN];
__device__ uint2 g_edge[EE];                    // (src, weight bits)
__device__ float g_psum[AGG_BLOCKS * DD];
__device__ float g_psq[AGG_BLOCKS * DD];
__device__ float g_psum2[128 * DD];
__device__ float g_psq2[128 * DD];
__device__ float g_scale[DD];
__device__ float g_shift[DD];
__device__ int   g_tick;

// ---------------- graph preprocessing ----------------

__global__ void zero_counts_k() {
    int i = blockIdx.x * blockDim.x + threadIdx.x;
    if (i < NN) g_counts[i] = 0;
}

__global__ void hist_k(const int* __restrict__ colp) {
    int i = blockIdx.x * blockDim.x + threadIdx.x;
    int stride = gridDim.x * blockDim.x;
    for (; i < EE; i += stride) atomicAdd(&g_counts[colp[i]], 1);
}

// block scan (+ dinv fused); g_off gets block-local exclusive, bsums block totals
__global__ void scan1_k() {
    __shared__ int sh[1024];
    int i = blockIdx.x * 1024 + threadIdx.x;
    int v = (i < NN) ? g_counts[i] : 0;
    if (i < NN) g_dinv[i] = rsqrtf((float)v + 1.0f);
    sh[threadIdx.x] = v;
    __syncthreads();
    #pragma unroll
    for (int o = 1; o < 1024; o <<= 1) {
        int t = (threadIdx.x >= o) ? sh[threadIdx.x - o] : 0;
        __syncthreads();
        sh[threadIdx.x] += t;
        __syncthreads();
    }
    if (i < NN) g_off[i] = sh[threadIdx.x] - v;
    if (threadIdx.x == 1023) g_bsums[blockIdx.x] = sh[1023];
}

// fused scan2+scan3: each block sums its predecessor bsums, offsets its slice
__global__ void scan23_k() {
    __shared__ int base;
    int b = blockIdx.x;
    if (threadIdx.x == 0) {
        int s = 0;
        for (int p = 0; p < b; p++) s += g_bsums[p];
        base = s;
    }
    __syncthreads();
    int i = b * 1024 + threadIdx.x;
    if (i < NN) {
        int v = g_off[i] + base;
        g_off[i] = v;
        g_cursor[i] = v;
    }
    if (i == 0) g_off[NN] = EE;
}

__global__ void scatter_k(const int* __restrict__ rowp,
                          const int* __restrict__ colp) {
    int i = blockIdx.x * blockDim.x + threadIdx.x;
    int stride = gridDim.x * blockDim.x;
    for (; i < EE; i += stride) {
        int r = rowp[i];
        int c = colp[i];
        float w = g_dinv[r] * g_dinv[c];
        int p = atomicAdd(&g_cursor[c], 1);
        g_edge[p] = make_uint2((unsigned)r, __float_as_uint(w));
    }
}

// ---------------- W split: slots 0,1,2 = W0,W1,W2 transposed hi/lo ---------------
__global__ void wsplit_k(const float* __restrict__ W0, const float* __restrict__ W1,
                         const float* __restrict__ W2) {
    int gidx = blockIdx.x * blockDim.x + threadIdx.x;
    if (gidx >= 3 * DD * DD) return;
    int m = gidx / (DD * DD);
    int idx = gidx - m * (DD * DD);
    const float* W = (m == 0) ? W0 : (m == 1) ? W1 : W2;
    int k = idx >> 7, n = idx & 127;
    float w = W[idx];
    __nv_bfloat16 h = __float2bfloat16_rn(w);
    float hf = __bfloat162float(h);
    __nv_bfloat16 l = __float2bfloat16_rn(w - hf);
    g_wth[m * DD * DD + n * DD + k] = __bfloat16_as_ushort(h);
    g_wtl[m * DD * DD + n * DD + k] = __bfloat16_as_ushort(l);
}

// ---------------- Wvo = Wv @ Wo (slot 3), bvo = bv @ Wo + bo ---------------------
__global__ void wvo_k(const float* __restrict__ Wv, const float* __restrict__ bv,
                      const float* __restrict__ Wo, const float* __restrict__ bo) {
    __shared__ float rowv[128];
    int t = threadIdx.x;
    if (blockIdx.x < 128) {
        int i = blockIdx.x;
        rowv[t] = Wv[i * 128 + t];
        __syncthreads();
        float s = 0.0f;
        #pragma unroll 8
        for (int k = 0; k < 128; k++) s += rowv[k] * Wo[k * 128 + t];
        __nv_bfloat16 h = __float2bfloat16_rn(s);
        float hf = __bfloat162float(h);
        __nv_bfloat16 l = __float2bfloat16_rn(s - hf);
        g_wth[3 * DD * DD + t * DD + i] = __bfloat16_as_ushort(h);
        g_wtl[3 * DD * DD + t * DD + i] = __bfloat16_as_ushort(l);
    } else {
        float s = bo[t];
        #pragma unroll 8
        for (int k = 0; k < 128; k++) s += bv[k] * Wo[k * 128 + t];
        g_bvo[t] = s;
    }
}

// ---------------- shared MMA helpers ----------------

__device__ __forceinline__ unsigned pack_bf16x2(float lo_elem, float hi_elem) {
    unsigned r;
    asm("cvt.rn.bf16x2.f32 %0, %1, %2;" : "=r"(r) : "f"(hi_elem), "f"(lo_elem));
    return r;
}

__device__ __forceinline__ void mma16816(float* c, const unsigned* a,
                                         unsigned b0, unsigned b1) {
    asm volatile(
        "mma.sync.aligned.m16n8k16.row.col.f32.bf16.bf16.f32 "
        "{%0,%1,%2,%3}, {%4,%5,%6,%7}, {%8,%9}, {%0,%1,%2,%3};"
        : "+f"(c[0]), "+f"(c[1]), "+f"(c[2]), "+f"(c[3])
        : "r"(a[0]), "r"(a[1]), "r"(a[2]), "r"(a[3]), "r"(b0), "r"(b1));
}

__device__ __forceinline__ void split2(float2 x, unsigned& hi, unsigned& lo) {
    hi = pack_bf16x2(x.x, x.y);
    float h0 = __uint_as_float(hi << 16);
    float h1 = __uint_as_float(hi & 0xFFFF0000u);
    lo = pack_bf16x2(x.x - h0, x.y - h1);
}

#define WT_STRIDE 68

// stage W^T hi/lo to padded smem
__device__ __forceinline__ void stage_w(unsigned* WhiS, unsigned* WloS,
                                        const unsigned short* Wthi,
                                        const unsigned short* Wtlo, int tid) {
    const unsigned* ghi = (const unsigned*)Wthi;
    const unsigned* glo = (const unsigned*)Wtlo;
    #pragma unroll
    for (int i = tid; i < DD * 64; i += 256) {
        int n = i >> 6, kw = i & 63;
        WhiS[n * WT_STRIDE + kw] = ghi[i];
        WloS[n * WT_STRIDE + kw] = glo[i];
    }
}

// ---------------- generic conv GEMM -------------------------------------------
// in: Ain (fp32) OR Ain16 (fp16). Res(fp32) != null: x = relu(in*scale+shift)+Res,
// rounded to fp16, stored to Store16. Output: C16 (fp16 gather table).
__global__ __launch_bounds__(256) void gemm_tc(
    const float* __restrict__ Ain, const __half2* __restrict__ Ain16,
    const float* __restrict__ Res, __half2* __restrict__ Store16,
    const unsigned short* __restrict__ Wthi, const unsigned short* __restrict__ Wtlo,
    __half2* __restrict__ C16, int M)
{
    extern __shared__ unsigned smw[];
    unsigned* WhiS = smw;
    unsigned* WloS = smw + DD * WT_STRIDE;
    float* sSc = (float*)(smw + 2 * DD * WT_STRIDE);
    float* sSh = sSc + DD;

    int tid = threadIdx.x;
    stage_w(WhiS, WloS, Wthi, Wtlo, tid);
    if (Res && tid < 128) { sSc[tid] = g_scale[tid]; sSh[tid] = g_shift[tid]; }
    __syncthreads();

    int warp = tid >> 5, lane = tid & 31;
    int g = lane >> 2, tig = lane & 3;
    int row0 = blockIdx.x * 128 + warp * 16 + g;
    int row1 = row0 + 8;
    bool v0 = row0 < M, v1 = row1 < M;
    const float* ar0 = Ain ? Ain + (size_t)row0 * DD : nullptr;
    const float* ar1 = Ain ? Ain + (size_t)row1 * DD : nullptr;
    const __half2* ah0 = Ain16 ? Ain16 + (size_t)row0 * 64 : nullptr;
    const __half2* ah1 = Ain16 ? Ain16 + (size_t)row1 * 64 : nullptr;

    float acc[16][4];
    #pragma unroll
    for (int nt = 0; nt < 16; nt++)
        #pragma unroll
        for (int i = 0; i < 4; i++) acc[nt][i] = 0.0f;

    const float2 z2 = make_float2(0.f, 0.f);

    #pragma unroll
    for (int kc = 0; kc < 8; kc++) {
        int k0 = kc * 16 + 2 * tig;
        float2 x0, x1, x2, x3;
        if (Ain16) {
            x0 = v0 ? __half22float2(ah0[(k0 >> 1)])     : z2;
            x1 = v1 ? __half22float2(ah1[(k0 >> 1)])     : z2;
            x2 = v0 ? __half22float2(ah0[(k0 >> 1) + 4]) : z2;
            x3 = v1 ? __half22float2(ah1[(k0 >> 1) + 4]) : z2;
        } else {
            x0 = v0 ? *(const float2*)(ar0 + k0)     : z2;
            x1 = v1 ? *(const float2*)(ar1 + k0)     : z2;
            x2 = v0 ? *(const float2*)(ar0 + k0 + 8) : z2;
            x3 = v1 ? *(const float2*)(ar1 + k0 + 8) : z2;
        }

        if (Res) {
            float2 scA = make_float2(sSc[k0], sSc[k0 + 1]);
            float2 shA = make_float2(sSh[k0], sSh[k0 + 1]);
            float2 scB = make_float2(sSc[k0 + 8], sSc[k0 + 9]);
            float2 shB = make_float2(sSh[k0 + 8], sSh[k0 + 9]);
            float2 r0 = v0 ? *(const float2*)(Res + (size_t)row0 * DD + k0)     : z2;
            float2 r1 = v1 ? *(const float2*)(Res + (size_t)row1 * DD + k0)     : z2;
            float2 r2 = v0 ? *(const float2*)(Res + (size_t)row0 * DD + k0 + 8) : z2;
            float2 r3 = v1 ? *(const float2*)(Res + (size_t)row1 * DD + k0 + 8) : z2;
            x0.x = fmaxf(fmaf(x0.x, scA.x, shA.x), 0.f) + r0.x;
            x0.y = fmaxf(fmaf(x0.y, scA.y, shA.y), 0.f) + r0.y;
            x1.x = fmaxf(fmaf(x1.x, scA.x, shA.x), 0.f) + r1.x;
            x1.y = fmaxf(fmaf(x1.y, scA.y, shA.y), 0.f) + r1.y;
            x2.x = fmaxf(fmaf(x2.x, scB.x, shB.x), 0.f) + r2.x;
            x2.y = fmaxf(fmaf(x2.y, scB.y, shB.y), 0.f) + r2.y;
            x3.x = fmaxf(fmaf(x3.x, scB.x, shB.x), 0.f) + r3.x;
            x3.y = fmaxf(fmaf(x3.y, scB.y, shB.y), 0.f) + r3.y;
            __half2 p0 = __floats2half2_rn(x0.x, x0.y);
            __half2 p1 = __floats2half2_rn(x1.x, x1.y);
            __half2 p2 = __floats2half2_rn(x2.x, x2.y);
            __half2 p3 = __floats2half2_rn(x3.x, x3.y);
            if (v0) {
                Store16[(size_t)row0 * 64 + (k0 >> 1)]     = p0;
                Store16[(size_t)row0 * 64 + (k0 >> 1) + 4] = p2;
            }
            if (v1) {
                Store16[(size_t)row1 * 64 + (k0 >> 1)]     = p1;
                Store16[(size_t)row1 * 64 + (k0 >> 1) + 4] = p3;
            }
            x0 = __half22float2(p0); x1 = __half22float2(p1);
            x2 = __half22float2(p2); x3 = __half22float2(p3);
        }

        unsigned ahi[4], alo[4];
        split2(x0, ahi[0], alo[0]);
        split2(x1, ahi[1], alo[1]);
        split2(x2, ahi[2], alo[2]);
        split2(x3, ahi[3], alo[3]);

        int kw = kc * 8 + tig;
        #pragma unroll
        for (int nt = 0; nt < 16; nt++) {
            int nrow = (nt * 8 + g) * WT_STRIDE + kw;
            unsigned bh0 = WhiS[nrow];
            unsigned bh1 = WhiS[nrow + 4];
            unsigned bl0 = WloS[nrow];
            unsigned bl1 = WloS[nrow + 4];
            mma16816(acc[nt], ahi, bh0, bh1);
            mma16816(acc[nt], ahi, bl0, bl1);
            mma16816(acc[nt], alo, bh0, bh1);
        }
    }

    #pragma unroll
    for (int nt = 0; nt < 16; nt++) {
        int col = nt * 8 + 2 * tig;
        if (v0) C16[(size_t)row0 * 64 + (col >> 1)] = __floats2half2_rn(acc[nt][0], acc[nt][1]);
        if (v1) C16[(size_t)row1 * 64 + (col >> 1)] = __floats2half2_rn(acc[nt][2], acc[nt][3]);
    }
}

// ---------------- attention GEMM: register-resident H + fused BN + LN ------------
// H = fp16(relu(bn1(Ain16)) + Res16) kept in registers; att = H @ Wvo;
// out C16 = fp16(LN(H + att + bvo)).
__global__ __launch_bounds__(256) void gemm_att(
    const __half2* __restrict__ Ain16, const __half2* __restrict__ Res16,
    const unsigned short* __restrict__ Wthi, const unsigned short* __restrict__ Wtlo,
    const float* __restrict__ bias, const float* __restrict__ lng,
    const float* __restrict__ lnb, __half2* __restrict__ C16, int M)
{
    extern __shared__ unsigned smw[];
    unsigned* WhiS = smw;
    unsigned* WloS = smw + DD * WT_STRIDE;
    float* sSc = (float*)(smw + 2 * DD * WT_STRIDE);
    float* sSh = sSc + DD;

    int tid = threadIdx.x;
    stage_w(WhiS, WloS, Wthi, Wtlo, tid);
    if (tid < 128) { sSc[tid] = g_scale[tid]; sSh[tid] = g_shift[tid]; }
    __syncthreads();

    int warp = tid >> 5, lane = tid & 31;
    int g = lane >> 2, tig = lane & 3;
    int row0 = blockIdx.x * 128 + warp * 16 + g;
    int row1 = row0 + 8;
    bool v0 = row0 < M, v1 = row1 < M;
    const __half2* ah0 = Ain16 + (size_t)row0 * 64;
    const __half2* ah1 = Ain16 + (size_t)row1 * 64;
    const __half2* rh0 = Res16 + (size_t)row0 * 64;
    const __half2* rh1 = Res16 + (size_t)row1 * 64;

    float acc[16][4];
    #pragma unroll
    for (int nt = 0; nt < 16; nt++)
        #pragma unroll
        for (int i = 0; i < 4; i++) acc[nt][i] = 0.0f;

    // packed H: hreg[kc][0]=x0(row0), [1]=x2(row0); hreg1: x1,x3 (row1)
    unsigned hreg0[8][2], hreg1[8][2];

    const float2 z2 = make_float2(0.f, 0.f);

    #pragma unroll
    for (int kc = 0; kc < 8; kc++) {
        int k0 = kc * 16 + 2 * tig;
        float2 x0 = v0 ? __half22float2(ah0[(k0 >> 1)])     : z2;
        float2 x1 = v1 ? __half22float2(ah1[(k0 >> 1)])     : z2;
        float2 x2 = v0 ? __half22float2(ah0[(k0 >> 1) + 4]) : z2;
        float2 x3 = v1 ? __half22float2(ah1[(k0 >> 1) + 4]) : z2;
        float2 r0 = v0 ? __half22float2(rh0[(k0 >> 1)])     : z2;
        float2 r1 = v1 ? __half22float2(rh1[(k0 >> 1)])     : z2;
        float2 r2 = v0 ? __half22float2(rh0[(k0 >> 1) + 4]) : z2;
        float2 r3 = v1 ? __half22float2(rh1[(k0 >> 1) + 4]) : z2;

        float2 scA = make_float2(sSc[k0], sSc[k0 + 1]);
        float2 shA = make_float2(sSh[k0], sSh[k0 + 1]);
        float2 scB = make_float2(sSc[k0 + 8], sSc[k0 + 9]);
        float2 shB = make_float2(sSh[k0 + 8], sSh[k0 + 9]);
        x0.x = fmaxf(fmaf(x0.x, scA.x, shA.x), 0.f) + r0.x;
        x0.y = fmaxf(fmaf(x0.y, scA.y, shA.y), 0.f) + r0.y;
        x1.x = fmaxf(fmaf(x1.x, scA.x, shA.x), 0.f) + r1.x;
        x1.y = fmaxf(fmaf(x1.y, scA.y, shA.y), 0.f) + r1.y;
        x2.x = fmaxf(fmaf(x2.x, scB.x, shB.x), 0.f) + r2.x;
        x2.y = fmaxf(fmaf(x2.y, scB.y, shB.y), 0.f) + r2.y;
        x3.x = fmaxf(fmaf(x3.x, scB.x, shB.x), 0.f) + r3.x;
        x3.y = fmaxf(fmaf(x3.y, scB.y, shB.y), 0.f) + r3.y;

        __half2 p0 = __floats2half2_rn(x0.x, x0.y);
        __half2 p1 = __floats2half2_rn(x1.x, x1.y);
        __half2 p2 = __floats2half2_rn(x2.x, x2.y);
        __half2 p3 = __floats2half2_rn(x3.x, x3.y);
        hreg0[kc][0] = *(const unsigned*)&p0;
        hreg0[kc][1] = *(const unsigned*)&p2;
        hreg1[kc][0] = *(const unsigned*)&p1;
        hreg1[kc][1] = *(const unsigned*)&p3;
        x0 = __half22float2(p0); x1 = __half22float2(p1);
        x2 = __half22float2(p2); x3 = __half22float2(p3);

        unsigned ahi[4], alo[4];
        split2(x0, ahi[0], alo[0]);
        split2(x1, ahi[1], alo[1]);
        split2(x2, ahi[2], alo[2]);
        split2(x3, ahi[3], alo[3]);

        int kw = kc * 8 + tig;
        #pragma unroll
        for (int nt = 0; nt < 16; nt++) {
            int nrow = (nt * 8 + g) * WT_STRIDE + kw;
            unsigned bh0 = WhiS[nrow];
            unsigned bh1 = WhiS[nrow + 4];
            unsigned bl0 = WloS[nrow];
            unsigned bl1 = WloS[nrow + 4];
            mma16816(acc[nt], ahi, bh0, bh1);
            mma16816(acc[nt], ahi, bl0, bl1);
            mma16816(acc[nt], alo, bh0, bh1);
        }
    }

    // LN epilogue: v = H + acc + bvo ; H from registers (nt -> kc=nt>>1, sel=nt&1)
    float s0 = 0.f, q0 = 0.f, s1 = 0.f, q1 = 0.f;
    #pragma unroll
    for (int nt = 0; nt < 16; nt++) {
        int col = nt * 8 + 2 * tig;
        float2 bb = *(const float2*)(bias + col);
        float2 h0 = __half22float2(*(const __half2*)&hreg0[nt >> 1][nt & 1]);
        float2 h1 = __half22float2(*(const __half2*)&hreg1[nt >> 1][nt & 1]);
        float v00 = h0.x + acc[nt][0] + bb.x;
        float v01 = h0.y + acc[nt][1] + bb.y;
        float v10 = h1.x + acc[nt][2] + bb.x;
        float v11 = h1.y + acc[nt][3] + bb.y;
        s0 += v00 + v01; q0 += v00 * v00 + v01 * v01;
        s1 += v10 + v11; q1 += v10 * v10 + v11 * v11;
    }
    #pragma unroll
    for (int o = 1; o <= 2; o <<= 1) {
        s0 += __shfl_xor_sync(0xFFFFFFFFu, s0, o);
        q0 += __shfl_xor_sync(0xFFFFFFFFu, q0, o);
        s1 += __shfl_xor_sync(0xFFFFFFFFu, s1, o);
        q1 += __shfl_xor_sync(0xFFFFFFFFu, q1, o);
    }
    float mu0 = s0 * (1.0f / 128.0f);
    float mu1 = s1 * (1.0f / 128.0f);
    float rs0 = rsqrtf(q0 * (1.0f / 128.0f) - mu0 * mu0 + 1e-5f);
    float rs1 = rsqrtf(q1 * (1.0f / 128.0f) - mu1 * mu1 + 1e-5f);
    #pragma unroll
    for (int nt = 0; nt < 16; nt++) {
        int col = nt * 8 + 2 * tig;
        float2 bb = *(const float2*)(bias + col);
        float2 gg = *(const float2*)(lng + col);
        float2 bt = *(const float2*)(lnb + col);
        if (v0) {
            float2 h0 = __half22float2(*(const __half2*)&hreg0[nt >> 1][nt & 1]);
            float v00 = h0.x + acc[nt][0] + bb.x;
            float v01 = h0.y + acc[nt][1] + bb.y;
            C16[(size_t)row0 * 64 + (col >> 1)] =
                __floats2half2_rn((v00 - mu0) * rs0 * gg.x + bt.x,
                                  (v01 - mu0) * rs0 * gg.y + bt.y);
        }
        if (v1) {
            float2 h1 = __half22float2(*(const __half2*)&hreg1[nt >> 1][nt & 1]);
            float v10 = h1.x + acc[nt][2] + bb.x;
            float v11 = h1.y + acc[nt][3] + bb.y;
            C16[(size_t)row1 * 64 + (col >> 1)] =
                __floats2half2_rn((v10 - mu1) * rs1 * gg.x + bt.x,
                                  (v11 - mu1) * rs1 * gg.y + bt.y);
        }
    }
}

// ---------------- aggregation: warp per node, 8-wide edge unroll ----------------
__global__ __launch_bounds__(256) void agg_k(
    const uint2* __restrict__ h16, const float* __restrict__ bias,
    float* __restrict__ out32, uint2* __restrict__ out16, int doStats)
{
    __shared__ float sPart[8][DD];
    int w = threadIdx.x >> 5;
    int n = blockIdx.x * 8 + w;          // grid exactly covers NN
    int l = threadIdx.x & 31;

    float di = g_dinv[n];
    float dii = di * di;
    uint2 us = h16[(size_t)n * 32 + l];
    float2 sa = __half22float2(*(const __half2*)&us.x);
    float2 sb = __half22float2(*(const __half2*)&us.y);
    float4 bb = *(const float4*)(bias + 4 * l);
    float a0 = fmaf(sa.x, dii, bb.x);
    float a1 = fmaf(sa.y, dii, bb.y);
    float a2 = fmaf(sb.x, dii, bb.z);
    float a3 = fmaf(sb.y, dii, bb.w);

    int j = g_off[n], e = g_off[n + 1];
    for (; j + 8 <= e; j += 8) {
        uint2 ed[8], u[8];
        #pragma unroll
        for (int q = 0; q < 8; q++) ed[q] = g_edge[j + q];
        #pragma unroll
        for (int q = 0; q < 8; q++) u[q] = h16[(size_t)ed[q].x * 32 + l];
        #pragma unroll
        for (int q = 0; q < 8; q++) {
            float wq = __uint_as_float(ed[q].y);
            float2 fa = __half22float2(*(const __half2*)&u[q].x);
            float2 fb = __half22float2(*(const __half2*)&u[q].y);
            a0 = fmaf(fa.x, wq, a0); a1 = fmaf(fa.y, wq, a1);
            a2 = fmaf(fb.x, wq, a2); a3 = fmaf(fb.y, wq, a3);
        }
    }
    for (; j < e; ++j) {
        uint2 ed = g_edge[j];
        float wq = __uint_as_float(ed.y);
        uint2 u = h16[(size_t)ed.x * 32 + l];
        float2 fa = __half22float2(*(const __half2*)&u.x);
        float2 fb = __half22float2(*(const __half2*)&u.y);
        a0 = fmaf(fa.x, wq, a0); a1 = fmaf(fa.y, wq, a1);
        a2 = fmaf(fb.x, wq, a2); a3 = fmaf(fb.y, wq, a3);
    }
    if (out32) *(float4*)(out32 + (size_t)n * DD + 4 * l) = make_float4(a0, a1, a2, a3);
    if (out16) {
        __half2 p0 = __floats2half2_rn(a0, a1);
        __half2 p1 = __floats2half2_rn(a2, a3);
        uint2 pk;
        pk.x = *(const unsigned*)&p0;
        pk.y = *(const unsigned*)&p1;
        out16[(size_t)n * 32 + l] = pk;
    }

    if (doStats) {
        *(float4*)&sPart[w][4 * l] = make_float4(a0, a1, a2, a3);
        __syncthreads();
        int t = threadIdx.x;
        if (t < DD) {
            float s = 0.f, q = 0.f;
            #pragma unroll
            for (int ww = 0; ww < 8; ww++) {
                float v = sPart[ww][t];
                s += v; q += v * v;
            }
            g_psum[blockIdx.x * DD + t] = s;
            g_psq[blockIdx.x * DD + t]  = q;
        }
    }
}

// ------- BN stat reduction (single kernel, last-block finishes scale/shift) ------
__global__ void reduce_bn_k(const float* __restrict__ g, const float* __restrict__ be) {
    int b = blockIdx.x;       // 0..127
    int t = threadIdx.x;      // 0..127
    int start = b * 98;
    int end = start + 98; if (end > AGG_BLOCKS) end = AGG_BLOCKS;
    float s = 0.f, q = 0.f;
    for (int p = start; p < end; p++) {
        s += g_psum[p * DD + t];
        q += g_psq[p * DD + t];
    }
    g_psum2[b * DD + t] = s;
    g_psq2[b * DD + t]  = q;
    __threadfence();
    __shared__ int isLast;
    __syncthreads();
    if (t == 0) isLast = (atomicAdd(&g_tick, 1) == 127);
    __syncthreads();
    if (isLast) {
        float ss = 0.f, qq = 0.f;
        for (int p = 0; p < 128; p++) {
            ss += g_psum2[p * DD + t];
            qq += g_psq2[p * DD + t];
        }
        float mu  = ss * (1.0f / NN);
        float var = qq * (1.0f / NN) - mu * mu;
        float sc  = g[t] * rsqrtf(var + 1e-5f);
        g_scale[t] = sc;
        g_shift[t] = be[t] - mu * sc;
        if (t == 0) g_tick = 0;
    }
}

// ---------------- launch ----------------
extern "C" void kernel_launch(void* const* d_in, const int* in_sizes, int n_in,
                              void* d_out, int out_size) {
    const float* x  = (const float*)d_in[0];
    const int*   ei = (const int*)d_in[1];   // int32 (JAX x64-disabled)
    const float* W0 = (const float*)d_in[2];  const float* b0 = (const float*)d_in[3];
    const float* W1 = (const float*)d_in[4];  const float* b1 = (const float*)d_in[5];
    const float* W2 = (const float*)d_in[6];  const float* b2 = (const float*)d_in[7];
    const float* g0 = (const float*)d_in[8];  const float* be0 = (const float*)d_in[9];
    const float* g1 = (const float*)d_in[10]; const float* be1 = (const float*)d_in[11];
    const float* Wv = (const float*)d_in[12]; const float* bv = (const float*)d_in[13];
    const float* Wo = (const float*)d_in[14]; const float* bo = (const float*)d_in[15];
    const float* lng = (const float*)d_in[16]; const float* lnb = (const float*)d_in[17];
    float* out = (float*)d_out;

    void *pH, *pB16, *pR16, *pL16, *pWh, *pWl, *pBvo;
    cudaGetSymbolAddress(&pH, g_h16);
    cudaGetSymbolAddress(&pB16, g_b16);
    cudaGetSymbolAddress(&pR16, g_r16);
    cudaGetSymbolAddress(&pL16, g_l16);
    cudaGetSymbolAddress(&pWh, g_wth);
    cudaGetSymbolAddress(&pWl, g_wtl);
    cudaGetSymbolAddress(&pBvo, g_bvo);
    __half2* H16 = (__half2*)pH;
    const uint2* H16u = (const uint2*)pH;
    uint2* B16u = (uint2*)pB16;
    const __half2* B16h = (const __half2*)pB16;
    __half2* R16 = (__half2*)pR16;
    __half2* L16 = (__half2*)pL16;
    const unsigned short* Wh = (const unsigned short*)pWh;
    const unsigned short* Wl = (const unsigned short*)pWl;
    const float* bvo = (const float*)pBvo;

    const int* rowp = ei;
    const int* colp = ei + EE;

    const int SCAN_BLOCKS = (NN + 1023) / 1024;   // 98
    const int GEMM_BLOCKS = (NN + 127) / 128;     // 782
    const int SMEM_W = 2 * DD * WT_STRIDE * 4 + 2 * DD * 4;   // 70656 B

    static int s_init = 0;
    static cudaStream_t s1, s2;
    static cudaEvent_t eFork, eJoin1, eJoin2;
    if (!s_init) {
        cudaFuncSetAttribute(gemm_tc, cudaFuncAttributeMaxDynamicSharedMemorySize, SMEM_W);
        cudaFuncSetAttribute(gemm_att, cudaFuncAttributeMaxDynamicSharedMemorySize, SMEM_W);
        cudaStreamCreateWithFlags(&s1, cudaStreamNonBlocking);
        cudaStreamCreateWithFlags(&s2, cudaStreamNonBlocking);
        cudaEventCreateWithFlags(&eFork, cudaEventDisableTiming);
        cudaEventCreateWithFlags(&eJoin1, cudaEventDisableTiming);
        cudaEventCreateWithFlags(&eJoin2, cudaEventDisableTiming);
        s_init = 1;
    }

    // --- fork: graph prep on s1, weight prep on s2 ---
    cudaEventRecord(eFork, 0);
    cudaStreamWaitEvent(s1, eFork, 0);
    cudaStreamWaitEvent(s2, eFork, 0);

    zero_counts_k<<<(NN + 255) / 256, 256, 0, s1>>>();
    hist_k<<<2048, 256, 0, s1>>>(colp);
    scan1_k<<<SCAN_BLOCKS, 1024, 0, s1>>>();
    scan23_k<<<SCAN_BLOCKS, 1024, 0, s1>>>();
    scatter_k<<<2048, 256, 0, s1>>>(rowp, colp);
    cudaEventRecord(eJoin1, s1);

    wsplit_k<<<(3 * DD * DD + 255) / 256, 256, 0, s2>>>(W0, W1, W2);
    wvo_k<<<129, 128, 0, s2>>>(Wv, bv, Wo, bo);
    cudaEventRecord(eJoin2, s2);

    const unsigned short* Wh0 = Wh;               const unsigned short* Wl0 = Wl;
    const unsigned short* Wh1 = Wh + 1 * DD * DD; const unsigned short* Wl1 = Wl + 1 * DD * DD;
    const unsigned short* Wh2 = Wh + 2 * DD * DD; const unsigned short* Wl2 = Wl + 2 * DD * DD;
    const unsigned short* Whv = Wh + 3 * DD * DD; const unsigned short* Wlv = Wl + 3 * DD * DD;

    // --- layer 0: H16 = fp16(x@W0)  (waits on weight prep only) ---
    cudaStreamWaitEvent(0, eJoin2, 0);
    gemm_tc<<<GEMM_BLOCKS, 256, SMEM_W>>>(x, nullptr, nullptr, nullptr,
                                          Wh0, Wl0, H16, NN);
    cudaStreamWaitEvent(0, eJoin1, 0);
    agg_k<<<AGG_BLOCKS, 256>>>(H16u, b0, nullptr, B16u, 1);
    reduce_bn_k<<<128, 128>>>(g0, be0);

    // --- layer 1: R16 = fp16(relu(bn0(B16)) + x); H16 = fp16(R16@W1) ---
    gemm_tc<<<GEMM_BLOCKS, 256, SMEM_W>>>(nullptr, B16h, x, R16,
                                          Wh1, Wl1, H16, NN);
    agg_k<<<AGG_BLOCKS, 256>>>(H16u, b1, nullptr, B16u, 1);
    reduce_bn_k<<<128, 128>>>(g1, be1);

    // --- attention + LN (register-resident H): L16 = fp16(LN(H + H@Wvo + bvo)) ---
    gemm_att<<<GEMM_BLOCKS, 256, SMEM_W>>>(B16h, (const __half2*)R16,
                                           Whv, Wlv, bvo, lng, lnb, L16, NN);

    // --- output conv: H16 = fp16(L16@W2) ; out = agg(H16) ---
    gemm_tc<<<GEMM_BLOCKS, 256, SMEM_W>>>(nullptr, (const __half2*)L16, nullptr,
                                          nullptr, Wh2, Wl2, H16, NN);
    agg_k<<<AGG_BLOCKS, 256>>>(H16u, b2, out, nullptr, 0);
}

// round 15
// speedup vs baseline: 1.4541x; 1.4541x over previous
#include <cuda_runtime.h>
#include <cuda_fp16.h>
#include <cuda_bf16.h>
#include <cstdint>

#define NN 100000
#define EE 1600000
#define DD 128
#define AGG_BLOCKS 12500   // NN / 8 exactly

// ---------------- scratch (device globals; no runtime allocation) ----------------
__device__ float g_bufA[(size_t)NN * DD];
__device__ float g_bufC[(size_t)NN * DD];
__device__ uint2 g_h16[(size_t)NN * 32];        // fp16 shadow table (GEMM out)
__device__ uint2 g_b16[(size_t)NN * 32];        // fp16 conv-agg output
__device__ uint2 g_l16[(size_t)NN * 32];        // fp16 LN output (final GEMM input)
__device__ unsigned short g_wth[4 * DD * DD];   // W^T hi (bf16 bits): W0,W1,W2,Wvo
__device__ unsigned short g_wtl[4 * DD * DD];   // W^T lo
__device__ float g_bvo[DD];
__device__ int   g_counts[NN];
__device__ int   g_off[NN + 1];
__device__ int   g_cursor[NN];
__device__ int   g_bsums[128];
__device__ float g_dinv[NN];
__device__ uint2 g_edge[EE];                    // (src, weight bits)
__device__ float g_psum[AGG_BLOCKS * DD];
__device__ float g_psq[AGG_BLOCKS * DD];
__device__ float g_psum2[128 * DD];
__device__ float g_psq2[128 * DD];
__device__ float g_scale[DD];
__device__ float g_shift[DD];
__device__ int   g_tick;

// ---------------- graph preprocessing ----------------

__global__ void zero_counts_k() {
    int i = blockIdx.x * blockDim.x + threadIdx.x;
    if (i < NN) g_counts[i] = 0;
}

__global__ void hist_k(const int* __restrict__ colp) {
    int i = blockIdx.x * blockDim.x + threadIdx.x;
    int stride = gridDim.x * blockDim.x;
    for (; i < EE; i += stride) atomicAdd(&g_counts[colp[i]], 1);
}

// block scan (+ dinv fused)
__global__ void scan1_k() {
    __shared__ int sh[1024];
    int i = blockIdx.x * 1024 + threadIdx.x;
    int v = (i < NN) ? g_counts[i] : 0;
    if (i < NN) g_dinv[i] = rsqrtf((float)v + 1.0f);
    sh[threadIdx.x] = v;
    __syncthreads();
    #pragma unroll
    for (int o = 1; o < 1024; o <<= 1) {
        int t = (threadIdx.x >= o) ? sh[threadIdx.x - o] : 0;
        __syncthreads();
        sh[threadIdx.x] += t;
        __syncthreads();
    }
    if (i < NN) g_off[i] = sh[threadIdx.x] - v;
    if (threadIdx.x == 1023) g_bsums[blockIdx.x] = sh[1023];
}

// fused scan2+scan3: each block sums its predecessor block totals, offsets slice
__global__ void scan23_k() {
    __shared__ int base;
    int b = blockIdx.x;
    if (threadIdx.x == 0) {
        int s = 0;
        for (int p = 0; p < b; p++) s += g_bsums[p];
        base = s;
    }
    __syncthreads();
    int i = b * 1024 + threadIdx.x;
    if (i < NN) {
        int v = g_off[i] + base;
        g_off[i] = v;
        g_cursor[i] = v;
    }
    if (i == 0) g_off[NN] = EE;
}

__global__ void scatter_k(const int* __restrict__ rowp,
                          const int* __restrict__ colp) {
    int i = blockIdx.x * blockDim.x + threadIdx.x;
    int stride = gridDim.x * blockDim.x;
    for (; i < EE; i += stride) {
        int r = rowp[i];
        int c = colp[i];
        float w = g_dinv[r] * g_dinv[c];
        int p = atomicAdd(&g_cursor[c], 1);
        g_edge[p] = make_uint2((unsigned)r, __float_as_uint(w));
    }
}

// ---------------- W split: slots 0,1,2 = W0,W1,W2 transposed hi/lo ---------------
__global__ void wsplit_k(const float* __restrict__ W0, const float* __restrict__ W1,
                         const float* __restrict__ W2) {
    int gidx = blockIdx.x * blockDim.x + threadIdx.x;
    if (gidx >= 3 * DD * DD) return;
    int m = gidx / (DD * DD);
    int idx = gidx - m * (DD * DD);
    const float* W = (m == 0) ? W0 : (m == 1) ? W1 : W2;
    int k = idx >> 7, n = idx & 127;
    float w = W[idx];
    __nv_bfloat16 h = __float2bfloat16_rn(w);
    float hf = __bfloat162float(h);
    __nv_bfloat16 l = __float2bfloat16_rn(w - hf);
    g_wth[m * DD * DD + n * DD + k] = __bfloat16_as_ushort(h);
    g_wtl[m * DD * DD + n * DD + k] = __bfloat16_as_ushort(l);
}

// ---------------- Wvo = Wv @ Wo (slot 3), bvo = bv @ Wo + bo ---------------------
__global__ void wvo_k(const float* __restrict__ Wv, const float* __restrict__ bv,
                      const float* __restrict__ Wo, const float* __restrict__ bo) {
    __shared__ float rowv[128];
    int t = threadIdx.x;
    if (blockIdx.x < 128) {
        int i = blockIdx.x;
        rowv[t] = Wv[i * 128 + t];
        __syncthreads();
        float s = 0.0f;
        #pragma unroll 8
        for (int k = 0; k < 128; k++) s += rowv[k] * Wo[k * 128 + t];
        __nv_bfloat16 h = __float2bfloat16_rn(s);
        float hf = __bfloat162float(h);
        __nv_bfloat16 l = __float2bfloat16_rn(s - hf);
        g_wth[3 * DD * DD + t * DD + i] = __bfloat16_as_ushort(h);
        g_wtl[3 * DD * DD + t * DD + i] = __bfloat16_as_ushort(l);
    } else {
        float s = bo[t];
        #pragma unroll 8
        for (int k = 0; k < 128; k++) s += bv[k] * Wo[k * 128 + t];
        g_bvo[t] = s;
    }
}

// ---------------- tensor-core GEMM (fused prologue/epilogue variants) ------------
//  - Ain16 != null: prologue input comes from an fp16 buffer.
//  - Res != null  : a = relu(in*scale+shift) + Res (BN apply), stored to Store.
//  - lng != null  : LayerNorm epilogue: C16 = fp16(LN(Store + acc + bias)) per row.
//  - C == null    : skip fp32 output write; C16 != null: write half2 copy.

__device__ __forceinline__ unsigned pack_bf16x2(float lo_elem, float hi_elem) {
    unsigned r;
    asm("cvt.rn.bf16x2.f32 %0, %1, %2;" : "=r"(r) : "f"(hi_elem), "f"(lo_elem));
    return r;
}

__device__ __forceinline__ void mma16816(float* c, const unsigned* a,
                                         unsigned b0, unsigned b1) {
    asm volatile(
        "mma.sync.aligned.m16n8k16.row.col.f32.bf16.bf16.f32 "
        "{%0,%1,%2,%3}, {%4,%5,%6,%7}, {%8,%9}, {%0,%1,%2,%3};"
        : "+f"(c[0]), "+f"(c[1]), "+f"(c[2]), "+f"(c[3])
        : "r"(a[0]), "r"(a[1]), "r"(a[2]), "r"(a[3]), "r"(b0), "r"(b1));
}

__device__ __forceinline__ void split2(float2 x, unsigned& hi, unsigned& lo) {
    hi = pack_bf16x2(x.x, x.y);
    float h0 = __uint_as_float(hi << 16);
    float h1 = __uint_as_float(hi & 0xFFFF0000u);
    lo = pack_bf16x2(x.x - h0, x.y - h1);
}

#define WT_STRIDE 68

__global__ __launch_bounds__(256) void gemm_tc(
    const float* __restrict__ Ain, const __half2* __restrict__ Ain16,
    const float* __restrict__ Res, float* __restrict__ Store,
    const unsigned short* __restrict__ Wthi, const unsigned short* __restrict__ Wtlo,
    const float* __restrict__ bias,
    const float* __restrict__ lng, const float* __restrict__ lnb,
    float* __restrict__ C, __half2* __restrict__ C16, int M)
{
    extern __shared__ unsigned smw[];
    unsigned* WhiS = smw;
    unsigned* WloS = smw + DD * WT_STRIDE;
    float* sSc = (float*)(smw + 2 * DD * WT_STRIDE);
    float* sSh = sSc + DD;

    int tid = threadIdx.x;
    const unsigned* ghi = (const unsigned*)Wthi;
    const unsigned* glo = (const unsigned*)Wtlo;
    #pragma unroll
    for (int i = tid; i < DD * 64; i += 256) {
        int n = i >> 6, kw = i & 63;
        WhiS[n * WT_STRIDE + kw] = ghi[i];
        WloS[n * WT_STRIDE + kw] = glo[i];
    }
    if (Res && tid < 128) { sSc[tid] = g_scale[tid]; sSh[tid] = g_shift[tid]; }
    __syncthreads();

    int warp = tid >> 5, lane = tid & 31;
    int g = lane >> 2, tig = lane & 3;
    int row0 = blockIdx.x * 128 + warp * 16 + g;
    int row1 = row0 + 8;
    bool v0 = row0 < M, v1 = row1 < M;
    const float* ar0 = Ain ? Ain + (size_t)row0 * DD : nullptr;
    const float* ar1 = Ain ? Ain + (size_t)row1 * DD : nullptr;
    const __half2* ah0 = Ain16 ? Ain16 + (size_t)row0 * 64 : nullptr;
    const __half2* ah1 = Ain16 ? Ain16 + (size_t)row1 * 64 : nullptr;

    float acc[16][4];
    #pragma unroll
    for (int nt = 0; nt < 16; nt++)
        #pragma unroll
        for (int i = 0; i < 4; i++) acc[nt][i] = 0.0f;

    const float2 z2 = make_float2(0.f, 0.f);

    #pragma unroll
    for (int kc = 0; kc < 8; kc++) {
        int k0 = kc * 16 + 2 * tig;
        float2 x0, x1, x2, x3;
        if (Ain16) {
            x0 = v0 ? __half22float2(ah0[(k0 >> 1)])     : z2;
            x1 = v1 ? __half22float2(ah1[(k0 >> 1)])     : z2;
            x2 = v0 ? __half22float2(ah0[(k0 >> 1) + 4]) : z2;
            x3 = v1 ? __half22float2(ah1[(k0 >> 1) + 4]) : z2;
        } else {
            x0 = v0 ? *(const float2*)(ar0 + k0)     : z2;
            x1 = v1 ? *(const float2*)(ar1 + k0)     : z2;
            x2 = v0 ? *(const float2*)(ar0 + k0 + 8) : z2;
            x3 = v1 ? *(const float2*)(ar1 + k0 + 8) : z2;
        }

        if (Res) {
            float2 scA = make_float2(sSc[k0], sSc[k0 + 1]);
            float2 shA = make_float2(sSh[k0], sSh[k0 + 1]);
            float2 scB = make_float2(sSc[k0 + 8], sSc[k0 + 9]);
            float2 shB = make_float2(sSh[k0 + 8], sSh[k0 + 9]);
            float2 r0 = v0 ? *(const float2*)(Res + (size_t)row0 * DD + k0)     : z2;
            float2 r1 = v1 ? *(const float2*)(Res + (size_t)row1 * DD + k0)     : z2;
            float2 r2 = v0 ? *(const float2*)(Res + (size_t)row0 * DD + k0 + 8) : z2;
            float2 r3 = v1 ? *(const float2*)(Res + (size_t)row1 * DD + k0 + 8) : z2;
            x0.x = fmaxf(fmaf(x0.x, scA.x, shA.x), 0.f) + r0.x;
            x0.y = fmaxf(fmaf(x0.y, scA.y, shA.y), 0.f) + r0.y;
            x1.x = fmaxf(fmaf(x1.x, scA.x, shA.x), 0.f) + r1.x;
            x1.y = fmaxf(fmaf(x1.y, scA.y, shA.y), 0.f) + r1.y;
            x2.x = fmaxf(fmaf(x2.x, scB.x, shB.x), 0.f) + r2.x;
            x2.y = fmaxf(fmaf(x2.y, scB.y, shB.y), 0.f) + r2.y;
            x3.x = fmaxf(fmaf(x3.x, scB.x, shB.x), 0.f) + r3.x;
            x3.y = fmaxf(fmaf(x3.y, scB.y, shB.y), 0.f) + r3.y;
            if (v0) {
                *(float2*)(Store + (size_t)row0 * DD + k0)     = x0;
                *(float2*)(Store + (size_t)row0 * DD + k0 + 8) = x2;
            }
            if (v1) {
                *(float2*)(Store + (size_t)row1 * DD + k0)     = x1;
                *(float2*)(Store + (size_t)row1 * DD + k0 + 8) = x3;
            }
        }

        unsigned ahi[4], alo[4];
        split2(x0, ahi[0], alo[0]);
        split2(x1, ahi[1], alo[1]);
        split2(x2, ahi[2], alo[2]);
        split2(x3, ahi[3], alo[3]);

        int kw = kc * 8 + tig;
        #pragma unroll
        for (int nt = 0; nt < 16; nt++) {
            int nrow = (nt * 8 + g) * WT_STRIDE + kw;
            unsigned bh0 = WhiS[nrow];
            unsigned bh1 = WhiS[nrow + 4];
            unsigned bl0 = WloS[nrow];
            unsigned bl1 = WloS[nrow + 4];
            mma16816(acc[nt], ahi, bh0, bh1);
            mma16816(acc[nt], ahi, bl0, bl1);
            mma16816(acc[nt], alo, bh0, bh1);
        }
    }

    if (!lng) {
        #pragma unroll
        for (int nt = 0; nt < 16; nt++) {
            int col = nt * 8 + 2 * tig;
            float2 bb = bias ? *(const float2*)(bias + col) : z2;
            float o0 = acc[nt][0] + bb.x, o1 = acc[nt][1] + bb.y;
            float o2 = acc[nt][2] + bb.x, o3 = acc[nt][3] + bb.y;
            if (v0) {
                if (C)   *(float2*)(C + (size_t)row0 * DD + col) = make_float2(o0, o1);
                if (C16) C16[(size_t)row0 * 64 + (col >> 1)] = __floats2half2_rn(o0, o1);
            }
            if (v1) {
                if (C)   *(float2*)(C + (size_t)row1 * DD + col) = make_float2(o2, o3);
                if (C16) C16[(size_t)row1 * 64 + (col >> 1)] = __floats2half2_rn(o2, o3);
            }
        }
    } else {
        // LayerNorm epilogue: v = Store(row) + acc + bias; LN across row (quad reduce)
        float s0 = 0.f, q0 = 0.f, s1 = 0.f, q1 = 0.f;
        #pragma unroll
        for (int nt = 0; nt < 16; nt++) {
            int col = nt * 8 + 2 * tig;
            float2 bb = *(const float2*)(bias + col);
            float2 h0 = v0 ? *(const float2*)(Store + (size_t)row0 * DD + col) : z2;
            float2 h1 = v1 ? *(const float2*)(Store + (size_t)row1 * DD + col) : z2;
            float v00 = h0.x + acc[nt][0] + bb.x;
            float v01 = h0.y + acc[nt][1] + bb.y;
            float v10 = h1.x + acc[nt][2] + bb.x;
            float v11 = h1.y + acc[nt][3] + bb.y;
            s0 += v00 + v01; q0 += v00 * v00 + v01 * v01;
            s1 += v10 + v11; q1 += v10 * v10 + v11 * v11;
        }
        #pragma unroll
        for (int o = 1; o <= 2; o <<= 1) {
            s0 += __shfl_xor_sync(0xFFFFFFFFu, s0, o);
            q0 += __shfl_xor_sync(0xFFFFFFFFu, q0, o);
            s1 += __shfl_xor_sync(0xFFFFFFFFu, s1, o);
            q1 += __shfl_xor_sync(0xFFFFFFFFu, q1, o);
        }
        float mu0 = s0 * (1.0f / 128.0f);
        float mu1 = s1 * (1.0f / 128.0f);
        float rs0 = rsqrtf(q0 * (1.0f / 128.0f) - mu0 * mu0 + 1e-5f);
        float rs1 = rsqrtf(q1 * (1.0f / 128.0f) - mu1 * mu1 + 1e-5f);
        #pragma unroll
        for (int nt = 0; nt < 16; nt++) {
            int col = nt * 8 + 2 * tig;
            float2 bb = *(const float2*)(bias + col);
            float2 gg = *(const float2*)(lng + col);
            float2 bt = *(const float2*)(lnb + col);
            if (v0) {
                float2 h0 = *(const float2*)(Store + (size_t)row0 * DD + col);
                float v00 = h0.x + acc[nt][0] + bb.x;
                float v01 = h0.y + acc[nt][1] + bb.y;
                C16[(size_t)row0 * 64 + (col >> 1)] =
                    __floats2half2_rn((v00 - mu0) * rs0 * gg.x + bt.x,
                                      (v01 - mu0) * rs0 * gg.y + bt.y);
            }
            if (v1) {
                float2 h1 = *(const float2*)(Store + (size_t)row1 * DD + col);
                float v10 = h1.x + acc[nt][2] + bb.x;
                float v11 = h1.y + acc[nt][3] + bb.y;
                C16[(size_t)row1 * 64 + (col >> 1)] =
                    __floats2half2_rn((v10 - mu1) * rs1 * gg.x + bt.x,
                                      (v11 - mu1) * rs1 * gg.y + bt.y);
            }
        }
    }
}

// ---------------- aggregation: warp per node, 8-wide edge unroll ----------------
__global__ __launch_bounds__(256) void agg_k(
    const uint2* __restrict__ h16, const float* __restrict__ bias,
    float* __restrict__ out32, uint2* __restrict__ out16, int doStats)
{
    __shared__ float sPart[8][DD];
    int w = threadIdx.x >> 5;
    int n = blockIdx.x * 8 + w;          // grid exactly covers NN
    int l = threadIdx.x & 31;

    float di = g_dinv[n];
    float dii = di * di;
    uint2 us = h16[(size_t)n * 32 + l];
    float2 sa = __half22float2(*(const __half2*)&us.x);
    float2 sb = __half22float2(*(const __half2*)&us.y);
    float4 bb = *(const float4*)(bias + 4 * l);
    float a0 = fmaf(sa.x, dii, bb.x);
    float a1 = fmaf(sa.y, dii, bb.y);
    float a2 = fmaf(sb.x, dii, bb.z);
    float a3 = fmaf(sb.y, dii, bb.w);

    int j = g_off[n], e = g_off[n + 1];
    for (; j + 8 <= e; j += 8) {
        uint2 ed[8], u[8];
        #pragma unroll
        for (int q = 0; q < 8; q++) ed[q] = g_edge[j + q];
        #pragma unroll
        for (int q = 0; q < 8; q++) u[q] = h16[(size_t)ed[q].x * 32 + l];
        #pragma unroll
        for (int q = 0; q < 8; q++) {
            float wq = __uint_as_float(ed[q].y);
            float2 fa = __half22float2(*(const __half2*)&u[q].x);
            float2 fb = __half22float2(*(const __half2*)&u[q].y);
            a0 = fmaf(fa.x, wq, a0); a1 = fmaf(fa.y, wq, a1);
            a2 = fmaf(fb.x, wq, a2); a3 = fmaf(fb.y, wq, a3);
        }
    }
    for (; j < e; ++j) {
        uint2 ed = g_edge[j];
        float wq = __uint_as_float(ed.y);
        uint2 u = h16[(size_t)ed.x * 32 + l];
        float2 fa = __half22float2(*(const __half2*)&u.x);
        float2 fb = __half22float2(*(const __half2*)&u.y);
        a0 = fmaf(fa.x, wq, a0); a1 = fmaf(fa.y, wq, a1);
        a2 = fmaf(fb.x, wq, a2); a3 = fmaf(fb.y, wq, a3);
    }
    if (out32) *(float4*)(out32 + (size_t)n * DD + 4 * l) = make_float4(a0, a1, a2, a3);
    if (out16) {
        __half2 p0 = __floats2half2_rn(a0, a1);
        __half2 p1 = __floats2half2_rn(a2, a3);
        uint2 pk;
        pk.x = *(const unsigned*)&p0;
        pk.y = *(const unsigned*)&p1;
        out16[(size_t)n * 32 + l] = pk;
    }

    if (doStats) {
        *(float4*)&sPart[w][4 * l] = make_float4(a0, a1, a2, a3);
        __syncthreads();
        int t = threadIdx.x;
        if (t < DD) {
            float s = 0.f, q = 0.f;
            #pragma unroll
            for (int ww = 0; ww < 8; ww++) {
                float v = sPart[ww][t];
                s += v; q += v * v;
            }
            g_psum[blockIdx.x * DD + t] = s;
            g_psq[blockIdx.x * DD + t]  = q;
        }
    }
}

// ------- BN stat reduction (single kernel, last-block finishes scale/shift) ------
__global__ void reduce_bn_k(const float* __restrict__ g, const float* __restrict__ be) {
    int b = blockIdx.x;       // 0..127
    int t = threadIdx.x;      // 0..127
    int start = b * 98;
    int end = start + 98; if (end > AGG_BLOCKS) end = AGG_BLOCKS;
    float s = 0.f, q = 0.f;
    for (int p = start; p < end; p++) {
        s += g_psum[p * DD + t];
        q += g_psq[p * DD + t];
    }
    g_psum2[b * DD + t] = s;
    g_psq2[b * DD + t]  = q;
    __threadfence();
    __shared__ int isLast;
    __syncthreads();
    if (t == 0) isLast = (atomicAdd(&g_tick, 1) == 127);
    __syncthreads();
    if (isLast) {
        float ss = 0.f, qq = 0.f;
        for (int p = 0; p < 128; p++) {
            ss += g_psum2[p * DD + t];
            qq += g_psq2[p * DD + t];
        }
        float mu  = ss * (1.0f / NN);
        float var = qq * (1.0f / NN) - mu * mu;
        float sc  = g[t] * rsqrtf(var + 1e-5f);
        g_scale[t] = sc;
        g_shift[t] = be[t] - mu * sc;
        if (t == 0) g_tick = 0;
    }
}

// ---------------- launch ----------------
extern "C" void kernel_launch(void* const* d_in, const int* in_sizes, int n_in,
                              void* d_out, int out_size) {
    const float* x  = (const float*)d_in[0];
    const int*   ei = (const int*)d_in[1];   // int32 (JAX x64-disabled)
    const float* W0 = (const float*)d_in[2];  const float* b0 = (const float*)d_in[3];
    const float* W1 = (const float*)d_in[4];  const float* b1 = (const float*)d_in[5];
    const float* W2 = (const float*)d_in[6];  const float* b2 = (const float*)d_in[7];
    const float* g0 = (const float*)d_in[8];  const float* be0 = (const float*)d_in[9];
    const float* g1 = (const float*)d_in[10]; const float* be1 = (const float*)d_in[11];
    const float* Wv = (const float*)d_in[12]; const float* bv = (const float*)d_in[13];
    const float* Wo = (const float*)d_in[14]; const float* bo = (const float*)d_in[15];
    const float* lng = (const float*)d_in[16]; const float* lnb = (const float*)d_in[17];
    float* out = (float*)d_out;

    void *pA, *pC, *pH, *pB16, *pL16, *pWh, *pWl, *pBvo;
    cudaGetSymbolAddress(&pA, g_bufA);
    cudaGetSymbolAddress(&pC, g_bufC);
    cudaGetSymbolAddress(&pH, g_h16);
    cudaGetSymbolAddress(&pB16, g_b16);
    cudaGetSymbolAddress(&pL16, g_l16);
    cudaGetSymbolAddress(&pWh, g_wth);
    cudaGetSymbolAddress(&pWl, g_wtl);
    cudaGetSymbolAddress(&pBvo, g_bvo);
    float* A = (float*)pA;
    float* C = (float*)pC;
    __half2* H16 = (__half2*)pH;
    const uint2* H16u = (const uint2*)pH;
    uint2* B16u = (uint2*)pB16;
    const __half2* B16h = (const __half2*)pB16;
    __half2* L16 = (__half2*)pL16;
    const unsigned short* Wh = (const unsigned short*)pWh;
    const unsigned short* Wl = (const unsigned short*)pWl;
    const float* bvo = (const float*)pBvo;

    const int* rowp = ei;
    const int* colp = ei + EE;

    const int SCAN_BLOCKS = (NN + 1023) / 1024;   // 98
    const int GEMM_BLOCKS = (NN + 127) / 128;     // 782
    const int SMEM_W = 2 * DD * WT_STRIDE * 4 + 2 * DD * 4;   // 70656 B

    static int s_init = 0;
    static cudaStream_t s1, s2;
    static cudaEvent_t eFork, eJoin1, eJoin2;
    if (!s_init) {
        cudaFuncSetAttribute(gemm_tc, cudaFuncAttributeMaxDynamicSharedMemorySize, SMEM_W);
        cudaStreamCreateWithFlags(&s1, cudaStreamNonBlocking);
        cudaStreamCreateWithFlags(&s2, cudaStreamNonBlocking);
        cudaEventCreateWithFlags(&eFork, cudaEventDisableTiming);
        cudaEventCreateWithFlags(&eJoin1, cudaEventDisableTiming);
        cudaEventCreateWithFlags(&eJoin2, cudaEventDisableTiming);
        s_init = 1;
    }

    // --- fork: graph prep on s1, weight prep on s2 ---
    cudaEventRecord(eFork, 0);
    cudaStreamWaitEvent(s1, eFork, 0);
    cudaStreamWaitEvent(s2, eFork, 0);

    zero_counts_k<<<(NN + 255) / 256, 256, 0, s1>>>();
    hist_k<<<2048, 256, 0, s1>>>(colp);
    scan1_k<<<SCAN_BLOCKS, 1024, 0, s1>>>();
    scan23_k<<<SCAN_BLOCKS, 1024, 0, s1>>>();
    scatter_k<<<2048, 256, 0, s1>>>(rowp, colp);
    cudaEventRecord(eJoin1, s1);

    wsplit_k<<<(3 * DD * DD + 255) / 256, 256, 0, s2>>>(W0, W1, W2);
    wvo_k<<<129, 128, 0, s2>>>(Wv, bv, Wo, bo);
    cudaEventRecord(eJoin2, s2);

    const unsigned short* Wh0 = Wh;               const unsigned short* Wl0 = Wl;
    const unsigned short* Wh1 = Wh + 1 * DD * DD; const unsigned short* Wl1 = Wl + 1 * DD * DD;
    const unsigned short* Wh2 = Wh + 2 * DD * DD; const unsigned short* Wl2 = Wl + 2 * DD * DD;
    const unsigned short* Whv = Wh + 3 * DD * DD; const unsigned short* Wlv = Wl + 3 * DD * DD;

    // --- layer 0: h16 = fp16(x@W0)  (waits on weight prep only) ---
    cudaStreamWaitEvent(0, eJoin2, 0);
    gemm_tc<<<GEMM_BLOCKS, 256, SMEM_W>>>(x, nullptr, nullptr, nullptr, Wh0, Wl0,
                                          nullptr, nullptr, nullptr, nullptr, H16, NN);
    // agg needs the CSR too
    cudaStreamWaitEvent(0, eJoin1, 0);
    agg_k<<<AGG_BLOCKS, 256>>>(H16u, b0, nullptr, B16u, 1);
    reduce_bn_k<<<128, 128>>>(g0, be0);

    // --- layer 1: BN0 apply fused in prologue (C = layer0 out), h16 = fp16(C@W1) --
    gemm_tc<<<GEMM_BLOCKS, 256, SMEM_W>>>(nullptr, B16h, x, C, Wh1, Wl1,
                                          nullptr, nullptr, nullptr, nullptr, H16, NN);
    agg_k<<<AGG_BLOCKS, 256>>>(H16u, b1, nullptr, B16u, 1);
    reduce_bn_k<<<128, 128>>>(g1, be1);

    // --- attention + LN: H = relu(bn(B16))+C (stored to A); att = H@Wvo + bvo ;
    //     L16 = fp16(LN(H + att)) ---
    gemm_tc<<<GEMM_BLOCKS, 256, SMEM_W>>>(nullptr, B16h, C, A, Whv, Wlv,
                                          bvo, lng, lnb, nullptr, L16, NN);

    // --- output conv: h16 = fp16(L16@W2) ; out = agg(h16) ---
    gemm_tc<<<GEMM_BLOCKS, 256, SMEM_W>>>(nullptr, (const __half2*)L16, nullptr,
                                          nullptr, Wh2, Wl2,
                                          nullptr, nullptr, nullptr, nullptr, H16, NN);
    agg_k<<<AGG_BLOCKS, 256>>>(H16u, b2, out, nullptr, 0);
}

// round 16
// speedup vs baseline: 1.5093x; 1.0379x over previous
#include <cuda_runtime.h>
#include <cuda_fp16.h>
#include <cuda_bf16.h>
#include <cstdint>

#define NN 100000
#define EE 1600000
#define DD 128
#define AGG_BLOCKS 12500   // NN / 8 exactly

// ---------------- scratch (device globals; no runtime allocation) ----------------
__device__ float g_bufA[(size_t)NN * DD];
__device__ float g_bufC[(size_t)NN * DD];
__device__ uint2 g_h16[(size_t)NN * 32];        // fp16 shadow table (GEMM out)
__device__ uint2 g_b16[(size_t)NN * 32];        // fp16 conv-agg output
__device__ uint2 g_l16[(size_t)NN * 32];        // fp16 LN output (final GEMM input)
__device__ unsigned short g_wth[4 * DD * DD];   // W^T hi (bf16 bits): W0,W1,W2,Wvo
__device__ unsigned short g_wtl[4 * DD * DD];   // W^T lo
__device__ float g_bvo[DD];
__device__ int   g_counts[NN];
__device__ int   g_off[NN + 1];
__device__ int   g_cursor[NN];
__device__ int   g_bsums[128];
__device__ float g_dinv[NN];
__device__ uint2 g_edge[EE];                    // (src, weight bits)
__device__ float g_psum[AGG_BLOCKS * DD];
__device__ float g_psq[AGG_BLOCKS * DD];
__device__ float g_psum2[128 * DD];
__device__ float g_psq2[128 * DD];
__device__ float g_scale[DD];
__device__ float g_shift[DD];
__device__ int   g_tick;

// ---------------- graph preprocessing ----------------

__global__ void hist_k(const int* __restrict__ colp) {
    int i = blockIdx.x * blockDim.x + threadIdx.x;
    int stride = gridDim.x * blockDim.x;
    for (; i < EE; i += stride) atomicAdd(&g_counts[colp[i]], 1);
}

// block scan (+ dinv fused)
__global__ void scan1_k() {
    __shared__ int sh[1024];
    int i = blockIdx.x * 1024 + threadIdx.x;
    int v = (i < NN) ? g_counts[i] : 0;
    if (i < NN) g_dinv[i] = rsqrtf((float)v + 1.0f);
    sh[threadIdx.x] = v;
    __syncthreads();
    #pragma unroll
    for (int o = 1; o < 1024; o <<= 1) {
        int t = (threadIdx.x >= o) ? sh[threadIdx.x - o] : 0;
        __syncthreads();
        sh[threadIdx.x] += t;
        __syncthreads();
    }
    if (i < NN) g_off[i] = sh[threadIdx.x] - v;
    if (threadIdx.x == 1023) g_bsums[blockIdx.x] = sh[1023];
}

// fused scan2+scan3: each block sums its predecessor block totals, offsets slice
__global__ void scan23_k() {
    __shared__ int base;
    int b = blockIdx.x;
    if (threadIdx.x == 0) {
        int s = 0;
        for (int p = 0; p < b; p++) s += g_bsums[p];
        base = s;
    }
    __syncthreads();
    int i = b * 1024 + threadIdx.x;
    if (i < NN) {
        int v = g_off[i] + base;
        g_off[i] = v;
        g_cursor[i] = v;
    }
    if (i == 0) g_off[NN] = EE;
}

__global__ void scatter_k(const int* __restrict__ rowp,
                          const int* __restrict__ colp) {
    int i = blockIdx.x * blockDim.x + threadIdx.x;
    int stride = gridDim.x * blockDim.x;
    for (; i < EE; i += stride) {
        int r = rowp[i];
        int c = colp[i];
        float w = g_dinv[r] * g_dinv[c];
        int p = atomicAdd(&g_cursor[c], 1);
        g_edge[p] = make_uint2((unsigned)r, __float_as_uint(w));
    }
}

// ---------------- W split: slots 0,1,2 = W0,W1,W2 transposed hi/lo ---------------
__global__ void wsplit_k(const float* __restrict__ W0, const float* __restrict__ W1,
                         const float* __restrict__ W2) {
    int gidx = blockIdx.x * blockDim.x + threadIdx.x;
    if (gidx >= 3 * DD * DD) return;
    int m = gidx / (DD * DD);
    int idx = gidx - m * (DD * DD);
    const float* W = (m == 0) ? W0 : (m == 1) ? W1 : W2;
    int k = idx >> 7, n = idx & 127;
    float w = W[idx];
    __nv_bfloat16 h = __float2bfloat16_rn(w);
    float hf = __bfloat162float(h);
    __nv_bfloat16 l = __float2bfloat16_rn(w - hf);
    g_wth[m * DD * DD + n * DD + k] = __bfloat16_as_ushort(h);
    g_wtl[m * DD * DD + n * DD + k] = __bfloat16_as_ushort(l);
}

// ---------------- Wvo = Wv @ Wo (slot 3), bvo = bv @ Wo + bo ---------------------
__global__ void wvo_k(const float* __restrict__ Wv, const float* __restrict__ bv,
                      const float* __restrict__ Wo, const float* __restrict__ bo) {
    __shared__ float rowv[128];
    int t = threadIdx.x;
    if (blockIdx.x < 128) {
        int i = blockIdx.x;
        rowv[t] = Wv[i * 128 + t];
        __syncthreads();
        float s = 0.0f;
        #pragma unroll 8
        for (int k = 0; k < 128; k++) s += rowv[k] * Wo[k * 128 + t];
        __nv_bfloat16 h = __float2bfloat16_rn(s);
        float hf = __bfloat162float(h);
        __nv_bfloat16 l = __float2bfloat16_rn(s - hf);
        g_wth[3 * DD * DD + t * DD + i] = __bfloat16_as_ushort(h);
        g_wtl[3 * DD * DD + t * DD + i] = __bfloat16_as_ushort(l);
    } else {
        float s = bo[t];
        #pragma unroll 8
        for (int k = 0; k < 128; k++) s += bv[k] * Wo[k * 128 + t];
        g_bvo[t] = s;
    }
}

// ---------------- tensor-core GEMM (fused prologue/epilogue variants) ------------
//  - Ain16 != null: prologue input comes from an fp16 buffer.
//  - Res != null  : a = relu(in*scale+shift) + Res (BN apply), stored to Store.
//  - lng != null  : LayerNorm epilogue: C16 = fp16(LN(Store + acc + bias)) per row.
//  - C == null    : skip fp32 output write; C16 != null: write half2 copy.
// PDL: W staging happens pre-sync (weights are >=2 dependency levels old);
// predecessor outputs (Ain/Ain16/Res/scale/shift) are read only post-sync.

__device__ __forceinline__ unsigned pack_bf16x2(float lo_elem, float hi_elem) {
    unsigned r;
    asm("cvt.rn.bf16x2.f32 %0, %1, %2;" : "=r"(r) : "f"(hi_elem), "f"(lo_elem));
    return r;
}

__device__ __forceinline__ void mma16816(float* c, const unsigned* a,
                                         unsigned b0, unsigned b1) {
    asm volatile(
        "mma.sync.aligned.m16n8k16.row.col.f32.bf16.bf16.f32 "
        "{%0,%1,%2,%3}, {%4,%5,%6,%7}, {%8,%9}, {%0,%1,%2,%3};"
        : "+f"(c[0]), "+f"(c[1]), "+f"(c[2]), "+f"(c[3])
        : "r"(a[0]), "r"(a[1]), "r"(a[2]), "r"(a[3]), "r"(b0), "r"(b1));
}

__device__ __forceinline__ void split2(float2 x, unsigned& hi, unsigned& lo) {
    hi = pack_bf16x2(x.x, x.y);
    float h0 = __uint_as_float(hi << 16);
    float h1 = __uint_as_float(hi & 0xFFFF0000u);
    lo = pack_bf16x2(x.x - h0, x.y - h1);
}

#define WT_STRIDE 68

__global__ __launch_bounds__(256) void gemm_tc(
    const float* __restrict__ Ain, const __half2* __restrict__ Ain16,
    const float* __restrict__ Res, float* __restrict__ Store,
    const unsigned short* __restrict__ Wthi, const unsigned short* __restrict__ Wtlo,
    const float* __restrict__ bias,
    const float* __restrict__ lng, const float* __restrict__ lnb,
    float* __restrict__ C, __half2* __restrict__ C16, int M)
{
    extern __shared__ unsigned smw[];
    unsigned* WhiS = smw;
    unsigned* WloS = smw + DD * WT_STRIDE;
    float* sSc = (float*)(smw + 2 * DD * WT_STRIDE);
    float* sSh = sSc + DD;

    int tid = threadIdx.x;
    if (tid == 0) cudaTriggerProgrammaticLaunchCompletion();
    // --- pre-sync: stage weights (written by long-completed prep) ---
    const unsigned* ghi = (const unsigned*)Wthi;
    const unsigned* glo = (const unsigned*)Wtlo;
    #pragma unroll
    for (int i = tid; i < DD * 64; i += 256) {
        int n = i >> 6, kw = i & 63;
        WhiS[n * WT_STRIDE + kw] = ghi[i];
        WloS[n * WT_STRIDE + kw] = glo[i];
    }
    // --- wait for predecessor (agg / reduce_bn) before touching its output ---
    cudaGridDependencySynchronize();
    if (Res && tid < 128) { sSc[tid] = g_scale[tid]; sSh[tid] = g_shift[tid]; }
    __syncthreads();

    int warp = tid >> 5, lane = tid & 31;
    int g = lane >> 2, tig = lane & 3;
    int row0 = blockIdx.x * 128 + warp * 16 + g;
    int row1 = row0 + 8;
    bool v0 = row0 < M, v1 = row1 < M;
    const float* ar0 = Ain ? Ain + (size_t)row0 * DD : nullptr;
    const float* ar1 = Ain ? Ain + (size_t)row1 * DD : nullptr;
    const __half2* ah0 = Ain16 ? Ain16 + (size_t)row0 * 64 : nullptr;
    const __half2* ah1 = Ain16 ? Ain16 + (size_t)row1 * 64 : nullptr;

    float acc[16][4];
    #pragma unroll
    for (int nt = 0; nt < 16; nt++)
        #pragma unroll
        for (int i = 0; i < 4; i++) acc[nt][i] = 0.0f;

    const float2 z2 = make_float2(0.f, 0.f);

    #pragma unroll
    for (int kc = 0; kc < 8; kc++) {
        int k0 = kc * 16 + 2 * tig;
        float2 x0, x1, x2, x3;
        if (Ain16) {
            x0 = v0 ? __half22float2(ah0[(k0 >> 1)])     : z2;
            x1 = v1 ? __half22float2(ah1[(k0 >> 1)])     : z2;
            x2 = v0 ? __half22float2(ah0[(k0 >> 1) + 4]) : z2;
            x3 = v1 ? __half22float2(ah1[(k0 >> 1) + 4]) : z2;
        } else {
            x0 = v0 ? *(const float2*)(ar0 + k0)     : z2;
            x1 = v1 ? *(const float2*)(ar1 + k0)     : z2;
            x2 = v0 ? *(const float2*)(ar0 + k0 + 8) : z2;
            x3 = v1 ? *(const float2*)(ar1 + k0 + 8) : z2;
        }

        if (Res) {
            float2 scA = make_float2(sSc[k0], sSc[k0 + 1]);
            float2 shA = make_float2(sSh[k0], sSh[k0 + 1]);
            float2 scB = make_float2(sSc[k0 + 8], sSc[k0 + 9]);
            float2 shB = make_float2(sSh[k0 + 8], sSh[k0 + 9]);
            float2 r0 = v0 ? *(const float2*)(Res + (size_t)row0 * DD + k0)     : z2;
            float2 r1 = v1 ? *(const float2*)(Res + (size_t)row1 * DD + k0)     : z2;
            float2 r2 = v0 ? *(const float2*)(Res + (size_t)row0 * DD + k0 + 8) : z2;
            float2 r3 = v1 ? *(const float2*)(Res + (size_t)row1 * DD + k0 + 8) : z2;
            x0.x = fmaxf(fmaf(x0.x, scA.x, shA.x), 0.f) + r0.x;
            x0.y = fmaxf(fmaf(x0.y, scA.y, shA.y), 0.f) + r0.y;
            x1.x = fmaxf(fmaf(x1.x, scA.x, shA.x), 0.f) + r1.x;
            x1.y = fmaxf(fmaf(x1.y, scA.y, shA.y), 0.f) + r1.y;
            x2.x = fmaxf(fmaf(x2.x, scB.x, shB.x), 0.f) + r2.x;
            x2.y = fmaxf(fmaf(x2.y, scB.y, shB.y), 0.f) + r2.y;
            x3.x = fmaxf(fmaf(x3.x, scB.x, shB.x), 0.f) + r3.x;
            x3.y = fmaxf(fmaf(x3.y, scB.y, shB.y), 0.f) + r3.y;
            if (v0) {
                *(float2*)(Store + (size_t)row0 * DD + k0)     = x0;
                *(float2*)(Store + (size_t)row0 * DD + k0 + 8) = x2;
            }
            if (v1) {
                *(float2*)(Store + (size_t)row1 * DD + k0)     = x1;
                *(float2*)(Store + (size_t)row1 * DD + k0 + 8) = x3;
            }
        }

        unsigned ahi[4], alo[4];
        split2(x0, ahi[0], alo[0]);
        split2(x1, ahi[1], alo[1]);
        split2(x2, ahi[2], alo[2]);
        split2(x3, ahi[3], alo[3]);

        int kw = kc * 8 + tig;
        #pragma unroll
        for (int nt = 0; nt < 16; nt++) {
            int nrow = (nt * 8 + g) * WT_STRIDE + kw;
            unsigned bh0 = WhiS[nrow];
            unsigned bh1 = WhiS[nrow + 4];
            unsigned bl0 = WloS[nrow];
            unsigned bl1 = WloS[nrow + 4];
            mma16816(acc[nt], ahi, bh0, bh1);
            mma16816(acc[nt], ahi, bl0, bl1);
            mma16816(acc[nt], alo, bh0, bh1);
        }
    }

    if (!lng) {
        #pragma unroll
        for (int nt = 0; nt < 16; nt++) {
            int col = nt * 8 + 2 * tig;
            float2 bb = bias ? *(const float2*)(bias + col) : z2;
            float o0 = acc[nt][0] + bb.x, o1 = acc[nt][1] + bb.y;
            float o2 = acc[nt][2] + bb.x, o3 = acc[nt][3] + bb.y;
            if (v0) {
                if (C)   *(float2*)(C + (size_t)row0 * DD + col) = make_float2(o0, o1);
                if (C16) C16[(size_t)row0 * 64 + (col >> 1)] = __floats2half2_rn(o0, o1);
            }
            if (v1) {
                if (C)   *(float2*)(C + (size_t)row1 * DD + col) = make_float2(o2, o3);
                if (C16) C16[(size_t)row1 * 64 + (col >> 1)] = __floats2half2_rn(o2, o3);
            }
        }
    } else {
        // LayerNorm epilogue: v = Store(row) + acc + bias; LN across row (quad reduce)
        float s0 = 0.f, q0 = 0.f, s1 = 0.f, q1 = 0.f;
        #pragma unroll
        for (int nt = 0; nt < 16; nt++) {
            int col = nt * 8 + 2 * tig;
            float2 bb = *(const float2*)(bias + col);
            float2 h0 = v0 ? *(const float2*)(Store + (size_t)row0 * DD + col) : z2;
            float2 h1 = v1 ? *(const float2*)(Store + (size_t)row1 * DD + col) : z2;
            float v00 = h0.x + acc[nt][0] + bb.x;
            float v01 = h0.y + acc[nt][1] + bb.y;
            float v10 = h1.x + acc[nt][2] + bb.x;
            float v11 = h1.y + acc[nt][3] + bb.y;
            s0 += v00 + v01; q0 += v00 * v00 + v01 * v01;
            s1 += v10 + v11; q1 += v10 * v10 + v11 * v11;
        }
        #pragma unroll
        for (int o = 1; o <= 2; o <<= 1) {
            s0 += __shfl_xor_sync(0xFFFFFFFFu, s0, o);
            q0 += __shfl_xor_sync(0xFFFFFFFFu, q0, o);
            s1 += __shfl_xor_sync(0xFFFFFFFFu, s1, o);
            q1 += __shfl_xor_sync(0xFFFFFFFFu, q1, o);
        }
        float mu0 = s0 * (1.0f / 128.0f);
        float mu1 = s1 * (1.0f / 128.0f);
        float rs0 = rsqrtf(q0 * (1.0f / 128.0f) - mu0 * mu0 + 1e-5f);
        float rs1 = rsqrtf(q1 * (1.0f / 128.0f) - mu1 * mu1 + 1e-5f);
        #pragma unroll
        for (int nt = 0; nt < 16; nt++) {
            int col = nt * 8 + 2 * tig;
            float2 bb = *(const float2*)(bias + col);
            float2 gg = *(const float2*)(lng + col);
            float2 bt = *(const float2*)(lnb + col);
            if (v0) {
                float2 h0 = *(const float2*)(Store + (size_t)row0 * DD + col);
                float v00 = h0.x + acc[nt][0] + bb.x;
                float v01 = h0.y + acc[nt][1] + bb.y;
                C16[(size_t)row0 * 64 + (col >> 1)] =
                    __floats2half2_rn((v00 - mu0) * rs0 * gg.x + bt.x,
                                      (v01 - mu0) * rs0 * gg.y + bt.y);
            }
            if (v1) {
                float2 h1 = *(const float2*)(Store + (size_t)row1 * DD + col);
                float v10 = h1.x + acc[nt][2] + bb.x;
                float v11 = h1.y + acc[nt][3] + bb.y;
                C16[(size_t)row1 * 64 + (col >> 1)] =
                    __floats2half2_rn((v10 - mu1) * rs1 * gg.x + bt.x,
                                      (v11 - mu1) * rs1 * gg.y + bt.y);
            }
        }
    }
}

// ---------------- aggregation: warp per node, 8-wide edge unroll ----------------
// PDL: CSR offsets/dinv/bias read pre-sync (prep-owned, >=2 levels back);
// h16 gathers only post-sync.
__global__ __launch_bounds__(256) void agg_k(
    const uint2* __restrict__ h16, const float* __restrict__ bias,
    float* __restrict__ out32, uint2* __restrict__ out16, int doStats)
{
    __shared__ float sPart[8][DD];
    int w = threadIdx.x >> 5;
    int n = blockIdx.x * 8 + w;          // grid exactly covers NN
    int l = threadIdx.x & 31;

    if (threadIdx.x == 0) cudaTriggerProgrammaticLaunchCompletion();
    // pre-sync: prep-owned metadata
    float di = g_dinv[n];
    float dii = di * di;
    int j = g_off[n], e = g_off[n + 1];
    float4 bb = *(const float4*)(bias + 4 * l);

    cudaGridDependencySynchronize();

    uint2 us = h16[(size_t)n * 32 + l];
    float2 sa = __half22float2(*(const __half2*)&us.x);
    float2 sb = __half22float2(*(const __half2*)&us.y);
    float a0 = fmaf(sa.x, dii, bb.x);
    float a1 = fmaf(sa.y, dii, bb.y);
    float a2 = fmaf(sb.x, dii, bb.z);
    float a3 = fmaf(sb.y, dii, bb.w);

    for (; j + 8 <= e; j += 8) {
        uint2 ed[8], u[8];
        #pragma unroll
        for (int q = 0; q < 8; q++) ed[q] = g_edge[j + q];
        #pragma unroll
        for (int q = 0; q < 8; q++) u[q] = h16[(size_t)ed[q].x * 32 + l];
        #pragma unroll
        for (int q = 0; q < 8; q++) {
            float wq = __uint_as_float(ed[q].y);
            float2 fa = __half22float2(*(const __half2*)&u[q].x);
            float2 fb = __half22float2(*(const __half2*)&u[q].y);
            a0 = fmaf(fa.x, wq, a0); a1 = fmaf(fa.y, wq, a1);
            a2 = fmaf(fb.x, wq, a2); a3 = fmaf(fb.y, wq, a3);
        }
    }
    for (; j < e; ++j) {
        uint2 ed = g_edge[j];
        float wq = __uint_as_float(ed.y);
        uint2 u = h16[(size_t)ed.x * 32 + l];
        float2 fa = __half22float2(*(const __half2*)&u.x);
        float2 fb = __half22float2(*(const __half2*)&u.y);
        a0 = fmaf(fa.x, wq, a0); a1 = fmaf(fa.y, wq, a1);
        a2 = fmaf(fb.x, wq, a2); a3 = fmaf(fb.y, wq, a3);
    }
    if (out32) *(float4*)(out32 + (size_t)n * DD + 4 * l) = make_float4(a0, a1, a2, a3);
    if (out16) {
        __half2 p0 = __floats2half2_rn(a0, a1);
        __half2 p1 = __floats2half2_rn(a2, a3);
        uint2 pk;
        pk.x = *(const unsigned*)&p0;
        pk.y = *(const unsigned*)&p1;
        out16[(size_t)n * 32 + l] = pk;
    }

    if (doStats) {
        *(float4*)&sPart[w][4 * l] = make_float4(a0, a1, a2, a3);
        __syncthreads();
        int t = threadIdx.x;
        if (t < DD) {
            float s = 0.f, q = 0.f;
            #pragma unroll
            for (int ww = 0; ww < 8; ww++) {
                float v = sPart[ww][t];
                s += v; q += v * v;
            }
            g_psum[blockIdx.x * DD + t] = s;
            g_psq[blockIdx.x * DD + t]  = q;
        }
    }
}

// ------- BN stat reduction (single kernel, last-block finishes scale/shift) ------
__global__ void reduce_bn_k(const float* __restrict__ g, const float* __restrict__ be) {
    if (threadIdx.x == 0) cudaTriggerProgrammaticLaunchCompletion();
    cudaGridDependencySynchronize();
    int b = blockIdx.x;       // 0..127
    int t = threadIdx.x;      // 0..127
    int start = b * 98;
    int end = start + 98; if (end > AGG_BLOCKS) end = AGG_BLOCKS;
    float s = 0.f, q = 0.f;
    for (int p = start; p < end; p++) {
        s += g_psum[p * DD + t];
        q += g_psq[p * DD + t];
    }
    g_psum2[b * DD + t] = s;
    g_psq2[b * DD + t]  = q;
    __threadfence();
    __shared__ int isLast;
    __syncthreads();
    if (t == 0) isLast = (atomicAdd(&g_tick, 1) == 127);
    __syncthreads();
    if (isLast) {
        float ss = 0.f, qq = 0.f;
        for (int p = 0; p < 128; p++) {
            ss += g_psum2[p * DD + t];
            qq += g_psq2[p * DD + t];
        }
        float mu  = ss * (1.0f / NN);
        float var = qq * (1.0f / NN) - mu * mu;
        float sc  = g[t] * rsqrtf(var + 1e-5f);
        g_scale[t] = sc;
        g_shift[t] = be[t] - mu * sc;
        if (t == 0) g_tick = 0;
    }
}

// ---------------- PDL launch helper ----------------
static inline void pdl_launch(const void* fn, int grid, int block, size_t smem,
                              void** args) {
    cudaLaunchConfig_t cfg = {};
    cfg.gridDim = dim3(grid, 1, 1);
    cfg.blockDim = dim3(block, 1, 1);
    cfg.dynamicSmemBytes = smem;
    cfg.stream = 0;
    cudaLaunchAttribute a[1];
    a[0].id = cudaLaunchAttributeProgrammaticStreamSerialization;
    a[0].val.programmaticStreamSerializationAllowed = 1;
    cfg.attrs = a;
    cfg.numAttrs = 1;
    cudaLaunchKernelExC(&cfg, fn, args);
}

// ---------------- launch ----------------
extern "C" void kernel_launch(void* const* d_in, const int* in_sizes, int n_in,
                              void* d_out, int out_size) {
    const float* x  = (const float*)d_in[0];
    const int*   ei = (const int*)d_in[1];   // int32 (JAX x64-disabled)
    const float* W0 = (const float*)d_in[2];  const float* b0 = (const float*)d_in[3];
    const float* W1 = (const float*)d_in[4];  const float* b1 = (const float*)d_in[5];
    const float* W2 = (const float*)d_in[6];  const float* b2 = (const float*)d_in[7];
    const float* g0 = (const float*)d_in[8];  const float* be0 = (const float*)d_in[9];
    const float* g1 = (const float*)d_in[10]; const float* be1 = (const float*)d_in[11];
    const float* Wv = (const float*)d_in[12]; const float* bv = (const float*)d_in[13];
    const float* Wo = (const float*)d_in[14]; const float* bo = (const float*)d_in[15];
    const float* lng = (const float*)d_in[16]; const float* lnb = (const float*)d_in[17];
    float* out = (float*)d_out;

    void *pA, *pC, *pH, *pB16, *pL16, *pWh, *pWl, *pBvo, *pCnt;
    cudaGetSymbolAddress(&pA, g_bufA);
    cudaGetSymbolAddress(&pC, g_bufC);
    cudaGetSymbolAddress(&pH, g_h16);
    cudaGetSymbolAddress(&pB16, g_b16);
    cudaGetSymbolAddress(&pL16, g_l16);
    cudaGetSymbolAddress(&pWh, g_wth);
    cudaGetSymbolAddress(&pWl, g_wtl);
    cudaGetSymbolAddress(&pBvo, g_bvo);
    cudaGetSymbolAddress(&pCnt, g_counts);
    float* A = (float*)pA;
    float* C = (float*)pC;
    __half2* H16 = (__half2*)pH;
    const uint2* H16u = (const uint2*)pH;
    uint2* B16u = (uint2*)pB16;
    const __half2* B16h = (const __half2*)pB16;
    __half2* L16 = (__half2*)pL16;
    const unsigned short* Wh = (const unsigned short*)pWh;
    const unsigned short* Wl = (const unsigned short*)pWl;
    const float* bvo = (const float*)pBvo;

    const int* rowp = ei;
    const int* colp = ei + EE;

    const int SCAN_BLOCKS = (NN + 1023) / 1024;   // 98
    const int GEMM_BLOCKS = (NN + 127) / 128;     // 782
    const int SMEM_W = 2 * DD * WT_STRIDE * 4 + 2 * DD * 4;   // 70656 B

    static int s_init = 0;
    static cudaStream_t s1, s2;
    static cudaEvent_t eFork, eJoin1, eJoin2;
    if (!s_init) {
        cudaFuncSetAttribute(gemm_tc, cudaFuncAttributeMaxDynamicSharedMemorySize, SMEM_W);
        cudaStreamCreateWithFlags(&s1, cudaStreamNonBlocking);
        cudaStreamCreateWithFlags(&s2, cudaStreamNonBlocking);
        cudaEventCreateWithFlags(&eFork, cudaEventDisableTiming);
        cudaEventCreateWithFlags(&eJoin1, cudaEventDisableTiming);
        cudaEventCreateWithFlags(&eJoin2, cudaEventDisableTiming);
        s_init = 1;
    }

    // --- fork: graph prep on s1, weight prep on s2 ---
    cudaEventRecord(eFork, 0);
    cudaStreamWaitEvent(s1, eFork, 0);
    cudaStreamWaitEvent(s2, eFork, 0);

    cudaMemsetAsync(pCnt, 0, NN * sizeof(int), s1);
    hist_k<<<2048, 256, 0, s1>>>(colp);
    scan1_k<<<SCAN_BLOCKS, 1024, 0, s1>>>();
    scan23_k<<<SCAN_BLOCKS, 1024, 0, s1>>>();
    scatter_k<<<2048, 256, 0, s1>>>(rowp, colp);
    cudaEventRecord(eJoin1, s1);

    wsplit_k<<<(3 * DD * DD + 255) / 256, 256, 0, s2>>>(W0, W1, W2);
    wvo_k<<<129, 128, 0, s2>>>(Wv, bv, Wo, bo);
    cudaEventRecord(eJoin2, s2);

    const unsigned short* Wh0 = Wh;               const unsigned short* Wl0 = Wl;
    const unsigned short* Wh1 = Wh + 1 * DD * DD; const unsigned short* Wl1 = Wl + 1 * DD * DD;
    const unsigned short* Wh2 = Wh + 2 * DD * DD; const unsigned short* Wl2 = Wl + 2 * DD * DD;
    const unsigned short* Whv = Wh + 3 * DD * DD; const unsigned short* Wlv = Wl + 3 * DD * DD;

    const float* nullf = nullptr;
    __half2* nullh = nullptr;
    float* nullfm = nullptr;
    int MM = NN;

    // --- layer 0: H16 = fp16(x@W0) — NORMAL launch (fresh event deps: weights) ---
    cudaStreamWaitEvent(0, eJoin2, 0);
    gemm_tc<<<GEMM_BLOCKS, 256, SMEM_W>>>(x, nullptr, nullptr, nullptr, Wh0, Wl0,
                                          nullptr, nullptr, nullptr, nullptr, H16, NN);
    // agg0 — NORMAL launch (fresh event dep: CSR)
    cudaStreamWaitEvent(0, eJoin1, 0);
    agg_k<<<AGG_BLOCKS, 256>>>(H16u, b0, nullptr, B16u, 1);

    // reduce_bn0 — PDL
    {
        const float* a0 = g0; const float* a1 = be0;
        void* args[] = {(void*)&a0, (void*)&a1};
        pdl_launch((const void*)reduce_bn_k, 128, 128, 0, args);
    }

    // --- layer 1: BN0 apply fused in prologue (C = layer0 out), H16 = fp16(C@W1) --
    {
        const float* aAin = nullptr; const __half2* aA16 = B16h;
        const float* aRes = x; float* aStore = C;
        const unsigned short* awh = Wh1; const unsigned short* awl = Wl1;
        void* args[] = {(void*)&aAin, (void*)&aA16, (void*)&aRes, (void*)&aStore,
                        (void*)&awh, (void*)&awl, (void*)&nullf, (void*)&nullf,
                        (void*)&nullf, (void*)&nullfm, (void*)&H16, (void*)&MM};
        pdl_launch((const void*)gemm_tc, GEMM_BLOCKS, 256, SMEM_W, args);
    }
    {
        const uint2* ah = H16u; const float* ab = b1;
        float* ao32 = nullptr; uint2* ao16 = B16u; int st = 1;
        void* args[] = {(void*)&ah, (void*)&ab, (void*)&ao32, (void*)&ao16, (void*)&st};
        pdl_launch((const void*)agg_k, AGG_BLOCKS, 256, 0, args);
    }
    {
        const float* a0 = g1; const float* a1 = be1;
        void* args[] = {(void*)&a0, (void*)&a1};
        pdl_launch((const void*)reduce_bn_k, 128, 128, 0, args);
    }

    // --- attention + LN: H = relu(bn(B16))+C (stored to A); att = H@Wvo + bvo ;
    //     L16 = fp16(LN(H + att)) ---
    {
        const float* aAin = nullptr; const __half2* aA16 = B16h;
        const float* aRes = C; float* aStore = A;
        const unsigned short* awh = Whv; const unsigned short* awl = Wlv;
        const float* ab = bvo; const float* alg = lng; const float* alb = lnb;
        void* args[] = {(void*)&aAin, (void*)&aA16, (void*)&aRes, (void*)&aStore,
                        (void*)&awh, (void*)&awl, (void*)&ab, (void*)&alg,
                        (void*)&alb, (void*)&nullfm, (void*)&L16, (void*)&MM};
        pdl_launch((const void*)gemm_tc, GEMM_BLOCKS, 256, SMEM_W, args);
    }

    // --- output conv: H16 = fp16(L16@W2) ; out = agg(H16) ---
    {
        const float* aAin = nullptr; const __half2* aA16 = (const __half2*)L16;
        const float* aRes = nullptr; float* aStore = nullptr;
        const unsigned short* awh = Wh2; const unsigned short* awl = Wl2;
        void* args[] = {(void*)&aAin, (void*)&aA16, (void*)&aRes, (void*)&aStore,
                        (void*)&awh, (void*)&awl, (void*)&nullf, (void*)&nullf,
                        (void*)&nullf, (void*)&nullfm, (void*)&H16, (void*)&MM};
        pdl_launch((const void*)gemm_tc, GEMM_BLOCKS, 256, SMEM_W, args);
    }
    {
        const uint2* ah = H16u; const float* ab = b2;
        float* ao32 = out; uint2* ao16 = nullptr; int st = 0;
        void* args[] = {(void*)&ah, (void*)&ab, (void*)&ao32, (void*)&ao16, (void*)&st};
        pdl_launch((const void*)agg_k, AGG_BLOCKS, 256, 0, args);
    }
}